// round 8
// baseline (speedup 1.0000x reference)
#include <cuda_runtime.h>
#include <cuda_fp16.h>
#include <math.h>
#include <stdint.h>

// Problem constants
#define FEAT_DIM 512
#define H_DIM    512
#define DEPTH    17
#define N_NODES  ((1 << DEPTH) - 1)   // 131071
#define GATE5    (5 * H_DIM)          // 2560
#define MAX_PREV (1 << (DEPTH - 2))   // 32768

// ---------------------------------------------------------------------------
// Scratch (static __device__ allocations; fp16 intermediates)
// ---------------------------------------------------------------------------
__device__ __half g_iofux[(size_t)N_NODES * GATE5];  // 671 MB
__device__ __half g_px   [(size_t)N_NODES * H_DIM];  // 134 MB
__device__ float  g_c    [(size_t)N_NODES * H_DIM];  // 268 MB (fp32 recurrence)
__device__ __half g_hh   [(size_t)MAX_PREV * GATE5]; // 168 MB

__device__ __forceinline__ uint32_t smem_u32(const void* p) {
    uint32_t a;
    asm("{ .reg .u64 t; cvta.to.shared.u64 t, %1; cvt.u32.u64 %0, t; }" : "=r"(a) : "l"(p));
    return a;
}

// ---------------------------------------------------------------------------
// fp16 mma GEMM, fp32 A/B in, fp16 C out, fp32 accumulate.
// C[M,N] = A[M,K] @ B[N,K]^T.  K%32==0, N%256==0, M edge clamped.
// BM=128, BN=256, BK=32. 256 thr = 8 warps (2x4), warp tile 64x64 = 4x8 mma.
// SMEM rows: 32 data halfs in 40-half stride (conflict-free LDSM).
// Double-buffered; ldmatrix fragment loads; pack to fp16 at SMEM store.
// ---------------------------------------------------------------------------
#define BM 128
#define BN 256
#define BK 32
#define LH 40                        // halfs per SMEM row
#define A_BUF_B (BM * LH * 2)        // 10240 bytes
#define B_BUF_B (BN * LH * 2)        // 20480 bytes
#define SMEM_GEMM (2 * A_BUF_B + 2 * B_BUF_B)   // 61440

__device__ __forceinline__ void mma_f16(float c[4],
                                        uint32_t a0, uint32_t a1, uint32_t a2, uint32_t a3,
                                        uint32_t b0, uint32_t b1)
{
    asm volatile(
        "mma.sync.aligned.m16n8k16.row.col.f32.f16.f16.f32 "
        "{%0,%1,%2,%3}, {%4,%5,%6,%7}, {%8,%9}, {%0,%1,%2,%3};\n"
        : "+f"(c[0]), "+f"(c[1]), "+f"(c[2]), "+f"(c[3])
        : "r"(a0), "r"(a1), "r"(a2), "r"(a3), "r"(b0), "r"(b1));
}
#define LDSM_X4(r0, r1, r2, r3, addr) \
    asm volatile("ldmatrix.sync.aligned.m8n8.x4.shared.b16 {%0,%1,%2,%3}, [%4];" \
                 : "=r"(r0), "=r"(r1), "=r"(r2), "=r"(r3) : "r"(addr))

__device__ __forceinline__ uint32_t pack2h(float lo, float hi) {
    __half2 h = __floats2half2_rn(lo, hi);
    return *(uint32_t*)&h;
}

__global__ void __launch_bounds__(256, 1) h16gemm_tn(
    const float* __restrict__ A, const float* __restrict__ B,
    __half* __restrict__ C, int M, int N, int K)
{
    extern __shared__ __align__(16) char sm[];
    __half* As[2] = { (__half*)(sm),            (__half*)(sm + A_BUF_B) };
    __half* Bs[2] = { (__half*)(sm + 2*A_BUF_B), (__half*)(sm + 2*A_BUF_B + B_BUF_B) };

    const int tid  = threadIdx.x;
    const int lane = tid & 31;
    const int wid  = tid >> 5;
    const int wm   = wid & 1;        // 64-row group
    const int wn   = wid >> 1;       // 64-col group
    const int gid  = lane >> 2;
    const int tig  = lane & 3;
    const int bm   = blockIdx.y * BM;
    const int bn   = blockIdx.x * BN;

    // Loaders. A: 2 thr/row, 16 floats each. B: 1 thr/row, 32 floats.
    const int arow = tid >> 1;             // 0..127
    const int akh  = (tid & 1) * 16;       // half (and float) offset 0/16
    int ar = bm + arow; if (ar >= M) ar = M - 1;
    const float* Ap = A + (size_t)ar * K + akh;
    const float* Bp = B + (size_t)(bn + tid) * K;

    // ldmatrix lane addresses (buffer 0)
    const uint32_t asB = smem_u32(As[0]);
    const uint32_t bsB = smem_u32(Bs[0]);
    uint32_t aAdr[4];
#pragma unroll
    for (int mt = 0; mt < 4; mt++) {
        int m0 = wm * 64 + mt * 16;
        aAdr[mt] = asB + (((m0 + (lane & 15)) * LH) + (lane >> 4) * 8) * 2;
    }
    uint32_t bAdr[4];
#pragma unroll
    for (int p = 0; p < 4; p++) {
        int n0 = wn * 64 + p * 16 + ((lane >> 4) << 3) + (lane & 7);
        bAdr[p] = bsB + (n0 * LH + (lane & 8)) * 2;
    }

    float acc[4][8][4];
#pragma unroll
    for (int mt = 0; mt < 4; mt++)
#pragma unroll
        for (int nt = 0; nt < 8; nt++)
#pragma unroll
            for (int r = 0; r < 4; r++) acc[mt][nt][r] = 0.f;

    float4 pa[4], pb[8];
    auto prefetch = [&](int s) {
        const int k0 = s * BK;
#pragma unroll
        for (int i = 0; i < 4; i++) pa[i] = *(const float4*)(Ap + k0 + i * 4);
#pragma unroll
        for (int i = 0; i < 8; i++) pb[i] = *(const float4*)(Bp + k0 + i * 4);
    };
    auto store = [&](int b) {
        uint4 v;
        v.x = pack2h(pa[0].x, pa[0].y); v.y = pack2h(pa[0].z, pa[0].w);
        v.z = pack2h(pa[1].x, pa[1].y); v.w = pack2h(pa[1].z, pa[1].w);
        *(uint4*)&As[b][arow * LH + akh] = v;
        v.x = pack2h(pa[2].x, pa[2].y); v.y = pack2h(pa[2].z, pa[2].w);
        v.z = pack2h(pa[3].x, pa[3].y); v.w = pack2h(pa[3].z, pa[3].w);
        *(uint4*)&As[b][arow * LH + akh + 8] = v;
        v.x = pack2h(pb[0].x, pb[0].y); v.y = pack2h(pb[0].z, pb[0].w);
        v.z = pack2h(pb[1].x, pb[1].y); v.w = pack2h(pb[1].z, pb[1].w);
        *(uint4*)&Bs[b][tid * LH] = v;
        v.x = pack2h(pb[2].x, pb[2].y); v.y = pack2h(pb[2].z, pb[2].w);
        v.z = pack2h(pb[3].x, pb[3].y); v.w = pack2h(pb[3].z, pb[3].w);
        *(uint4*)&Bs[b][tid * LH + 8] = v;
        v.x = pack2h(pb[4].x, pb[4].y); v.y = pack2h(pb[4].z, pb[4].w);
        v.z = pack2h(pb[5].x, pb[5].y); v.w = pack2h(pb[5].z, pb[5].w);
        *(uint4*)&Bs[b][tid * LH + 16] = v;
        v.x = pack2h(pb[6].x, pb[6].y); v.y = pack2h(pb[6].z, pb[6].w);
        v.z = pack2h(pb[7].x, pb[7].y); v.w = pack2h(pb[7].z, pb[7].w);
        *(uint4*)&Bs[b][tid * LH + 24] = v;
    };

    prefetch(0);
    store(0);
    __syncthreads();

    const int nst = K / BK;          // 16
    for (int s = 0; s < nst; s++) {
        const int b = s & 1;
        const uint32_t ao = b * A_BUF_B;
        const uint32_t bo = b * B_BUF_B;
        if (s + 1 < nst) prefetch(s + 1);

#pragma unroll
        for (int ks = 0; ks < 2; ks++) {
            const uint32_t ko = ks * 32;       // 16 halfs = 32 bytes
            uint32_t af[4][4];
#pragma unroll
            for (int mt = 0; mt < 4; mt++)
                LDSM_X4(af[mt][0], af[mt][1], af[mt][2], af[mt][3], aAdr[mt] + ao + ko);
            uint32_t bf[8][2];
#pragma unroll
            for (int p = 0; p < 4; p++)
                LDSM_X4(bf[2*p][0], bf[2*p][1], bf[2*p+1][0], bf[2*p+1][1],
                        bAdr[p] + bo + ko);
#pragma unroll
            for (int mt = 0; mt < 4; mt++)
#pragma unroll
                for (int nt = 0; nt < 8; nt++)
                    mma_f16(acc[mt][nt], af[mt][0], af[mt][1], af[mt][2], af[mt][3],
                            bf[nt][0], bf[nt][1]);
        }

        if (s + 1 < nst) {
            store(b ^ 1);
            __syncthreads();
        }
    }

    // Epilogue: fp16 half2 stores
#pragma unroll
    for (int mt = 0; mt < 4; mt++) {
        int r0 = bm + wm * 64 + mt * 16 + gid;
        int r1 = r0 + 8;
#pragma unroll
        for (int nt = 0; nt < 8; nt++) {
            int col = bn + wn * 64 + nt * 8 + tig * 2;
            if (r0 < M)
                *(__half2*)(C + (size_t)r0 * N + col) = __floats2half2_rn(acc[mt][nt][0], acc[mt][nt][1]);
            if (r1 < M)
                *(__half2*)(C + (size_t)r1 * N + col) = __floats2half2_rn(acc[mt][nt][2], acc[mt][nt][3]);
        }
    }
}

// ---------------------------------------------------------------------------
// Small-M fp32 GEMM (fp16 out): 16 cols/block x 16 lanes/col, shfl reduce.
// grid = (N/16, M).
// ---------------------------------------------------------------------------
__global__ void __launch_bounds__(256) small_gemm_tn(
    const float* __restrict__ A, const float* __restrict__ B,
    __half* __restrict__ C, int N, int K)
{
    __shared__ float Arow[FEAT_DIM];
    const int tid  = threadIdx.x;
    const int lane = tid & 31;
    const int wid  = tid >> 5;
    const int m    = blockIdx.y;

    if (tid < FEAT_DIM / 4)
        ((float4*)Arow)[tid] = ((const float4*)(A + (size_t)m * K))[tid];
    __syncthreads();

    const int col = blockIdx.x * 16 + wid * 2 + (lane >> 4);
    const int hl  = lane & 15;

    const float4* Br = (const float4*)(B + (size_t)col * K) + hl;
    const float4* Ar = (const float4*)Arow + hl;
    float s = 0.f;
#pragma unroll
    for (int i = 0; i < 8; i++) {
        float4 b = Br[i * 16];
        float4 a = Ar[i * 16];
        s += a.x * b.x + a.y * b.y + a.z * b.z + a.w * b.w;
    }
#pragma unroll
    for (int off = 8; off >= 1; off >>= 1)
        s += __shfl_xor_sync(0xffffffff, s, off);
    if (hl == 0)
        C[(size_t)m * N + col] = __float2half_rn(s);
}

// ---------------------------------------------------------------------------
// Per-level fused gate/elementwise kernel (fp16 intermediates in, fp32 out)
// ---------------------------------------------------------------------------
__device__ __forceinline__ float sigf(float x) { return 1.f / (1.f + expf(-x)); }
__device__ __forceinline__ float4 f4add(float4 a, float4 b) {
    return make_float4(a.x + b.x, a.y + b.y, a.z + b.z, a.w + b.w);
}
__device__ __forceinline__ float4 loadh4(const __half* p) {
    __half2 a = *(const __half2*)p;
    __half2 b = *(const __half2*)(p + 2);
    float2 fa = __half22float2(a), fb = __half22float2(b);
    return make_float4(fa.x, fa.y, fb.x, fb.y);
}

__global__ void __launch_bounds__(256) lstm_level_kernel(
    const float* __restrict__ iofux_b, const float* __restrict__ iofuh_b,
    const float* __restrict__ px_b, float* __restrict__ out,
    int start, int n, int hasPrev)
{
    int idx = blockIdx.x * 256 + threadIdx.x;
    int total = n * (H_DIM / 4);
    if (idx >= total) return;

    int j  = idx >> 7;
    int t4 = idx & 127;
    size_t g = (size_t)start + j;

    const __half* gx = g_iofux + g * GATE5 + t4 * 4;
    float4 vi = loadh4(gx);
    float4 vo = loadh4(gx + 512);
    float4 vf = loadh4(gx + 1024);
    float4 vu = loadh4(gx + 1536);
    float4 vr = loadh4(gx + 2048);

    float4 pc = make_float4(0.f, 0.f, 0.f, 0.f);
    if (hasPrev) {
        const __half* gh = g_hh + (size_t)(j >> 1) * GATE5 + t4 * 4;
        vi = f4add(vi, loadh4(gh));
        vo = f4add(vo, loadh4(gh + 512));
        vf = f4add(vf, loadh4(gh + 1024));
        vu = f4add(vu, loadh4(gh + 1536));
        vr = f4add(vr, loadh4(gh + 2048));
        size_t parent = (g - 1) >> 1;
        pc = ((const float4*)g_c)[parent * 128 + t4];
    }

    const float4* bx = (const float4*)iofux_b;
    const float4* bh = (const float4*)iofuh_b;
    vi = f4add(vi, f4add(bx[t4],       bh[t4]));
    vo = f4add(vo, f4add(bx[128 + t4], bh[128 + t4]));
    vf = f4add(vf, f4add(bx[256 + t4], bh[256 + t4]));
    vu = f4add(vu, f4add(bx[384 + t4], bh[384 + t4]));
    vr = f4add(vr, f4add(bx[512 + t4], bh[512 + t4]));

    float4 px4 = f4add(loadh4(g_px + g * H_DIM + t4 * 4),
                       ((const float4*)px_b)[t4]);

    float4 c4, h4;
#define GATE(C) {                                                     \
        float i_ = sigf(vi.C); float o_ = sigf(vo.C);                 \
        float f_ = sigf(vf.C); float u_ = tanhf(vu.C);                \
        float r_ = sigf(vr.C);                                        \
        float c_ = i_ * u_ + f_ * pc.C;                               \
        float h_ = o_ * tanhf(c_);                                    \
        c4.C = c_; h4.C = r_ * h_ + (1.f - r_) * px4.C; }
    GATE(x) GATE(y) GATE(z) GATE(w)
#undef GATE

    ((float4*)g_c)[g * 128 + t4] = c4;
    ((float4*)out)[g * 128 + t4] = h4;
}

// ---------------------------------------------------------------------------
// kernel_launch
// ---------------------------------------------------------------------------
extern "C" void kernel_launch(void* const* d_in, const int* in_sizes, int n_in,
                              void* d_out, int out_size)
{
    const float* features = (const float*)d_in[0];
    const float* px_w     = (const float*)d_in[1];
    const float* px_b     = (const float*)d_in[2];
    const float* iofux_w  = (const float*)d_in[3];
    const float* iofux_b  = (const float*)d_in[4];
    const float* iofuh_w  = (const float*)d_in[5];
    const float* iofuh_b  = (const float*)d_in[6];
    float* out = (float*)d_out;

    __half *iofux_p = nullptr, *px_p = nullptr, *hh_p = nullptr;
    cudaGetSymbolAddress((void**)&iofux_p, g_iofux);
    cudaGetSymbolAddress((void**)&px_p,    g_px);
    cudaGetSymbolAddress((void**)&hh_p,    g_hh);

    static bool attrSet = false;
    if (!attrSet) {
        cudaFuncSetAttribute(h16gemm_tn, cudaFuncAttributeMaxDynamicSharedMemorySize, SMEM_GEMM);
        attrSet = true;
    }

    dim3 blk(256);

    // px = feats @ px_w.T   [N_NODES, 512]
    {
        dim3 grid(H_DIM / BN, (N_NODES + BM - 1) / BM);
        h16gemm_tn<<<grid, blk, SMEM_GEMM>>>(features, px_w, px_p, N_NODES, H_DIM, FEAT_DIM);
    }
    // iofux = feats @ iofux_w.T  [N_NODES, 2560]
    {
        dim3 grid(GATE5 / BN, (N_NODES + BM - 1) / BM);
        h16gemm_tn<<<grid, blk, SMEM_GEMM>>>(features, iofux_w, iofux_p, N_NODES, GATE5, FEAT_DIM);
    }

    for (int d = 0; d < DEPTH; d++) {
        int n = 1 << d;
        int start = n - 1;
        if (d > 0) {
            int Md = n >> 1;
            int startPrev = Md - 1;
            const float* Aprev = out + (size_t)startPrev * H_DIM;
            if (Md <= 64) {
                dim3 grid(GATE5 / 16, Md);
                small_gemm_tn<<<grid, 256>>>(Aprev, iofuh_w, hh_p, GATE5, FEAT_DIM);
            } else {
                dim3 grid(GATE5 / BN, (Md + BM - 1) / BM);
                h16gemm_tn<<<grid, blk, SMEM_GEMM>>>(Aprev, iofuh_w, hh_p, Md, GATE5, FEAT_DIM);
            }
        }
        int total = n * (H_DIM / 4);
        int nb = (total + 255) / 256;
        lstm_level_kernel<<<nb, blk>>>(iofux_b, iofuh_b, px_b, out,
                                       start, n, d > 0 ? 1 : 0);
    }
}

// round 11
// speedup vs baseline: 1.1868x; 1.1868x over previous
#include <cuda_runtime.h>
#include <cuda_fp16.h>
#include <math.h>
#include <stdint.h>

// Problem constants
#define FEAT_DIM 512
#define H_DIM    512
#define DEPTH    17
#define N_NODES  ((1 << DEPTH) - 1)   // 131071
#define GATE5    (5 * H_DIM)          // 2560
#define MAX_PREV (1 << (DEPTH - 2))   // 32768

// ---------------------------------------------------------------------------
// Scratch (static __device__ allocations; fp16 intermediates, fp32 recurrence)
// ---------------------------------------------------------------------------
__device__ __half g_iofux[(size_t)N_NODES * GATE5];  // 671 MB
__device__ __half g_px   [(size_t)N_NODES * H_DIM];  // 134 MB
__device__ float  g_c    [(size_t)N_NODES * H_DIM];  // 268 MB
__device__ __half g_hh   [(size_t)MAX_PREV * GATE5]; // 168 MB

__device__ __forceinline__ uint32_t smem_u32(const void* p) {
    uint32_t a;
    asm("{ .reg .u64 t; cvta.to.shared.u64 t, %1; cvt.u32.u64 %0, t; }" : "=r"(a) : "l"(p));
    return a;
}

// ---------------------------------------------------------------------------
// fp16 mma GEMM with ldmatrix (round-6 validated structure), fp16 C out.
// C[M,N] = A[M,K] @ B[N,K]^T. Block 128x128, BK=16, 8 warps, warp 32x64.
// ---------------------------------------------------------------------------
#define BM 128
#define BN 128
#define BK 16
#define LH 40    // halfs per SMEM row

__device__ __forceinline__ void mma_f16(float c[4],
                                        uint32_t a0, uint32_t a1, uint32_t a2, uint32_t a3,
                                        uint32_t b0, uint32_t b1)
{
    asm volatile(
        "mma.sync.aligned.m16n8k16.row.col.f32.f16.f16.f32 "
        "{%0,%1,%2,%3}, {%4,%5,%6,%7}, {%8,%9}, {%0,%1,%2,%3};\n"
        : "+f"(c[0]), "+f"(c[1]), "+f"(c[2]), "+f"(c[3])
        : "r"(a0), "r"(a1), "r"(a2), "r"(a3), "r"(b0), "r"(b1));
}
#define LDSM_X4(r0, r1, r2, r3, addr) \
    asm volatile("ldmatrix.sync.aligned.m8n8.x4.shared.b16 {%0,%1,%2,%3}, [%4];" \
                 : "=r"(r0), "=r"(r1), "=r"(r2), "=r"(r3) : "r"(addr))

__device__ __forceinline__ uint32_t pack2h(float lo, float hi) {
    __half2 h = __floats2half2_rn(lo, hi);
    return *(uint32_t*)&h;
}

__global__ void __launch_bounds__(256, 2) h16gemm_tn(
    const float* __restrict__ A, const float* __restrict__ B,
    __half* __restrict__ C, int M, int N, int K)
{
    __shared__ __align__(16) __half As[2][BM * LH];
    __shared__ __align__(16) __half Bs[2][BN * LH];

    const int tid  = threadIdx.x;
    const int lane = tid & 31;
    const int wid  = tid >> 5;
    const int wm   = wid & 3;        // warp row group (32 rows)
    const int wn   = wid >> 2;       // warp col group (64 cols)
    const int gid  = lane >> 2;
    const int tig  = lane & 3;
    const int bm   = blockIdx.y * BM;
    const int bn   = blockIdx.x * BN;

    const int lrow = tid >> 1;             // 0..127
    const int lh   = (tid & 1) * 8;        // k offset 0 or 8

    int ar = bm + lrow; if (ar >= M) ar = M - 1;
    const float* Ap = A + (size_t)ar * K + lh;
    const float* Bp = B + (size_t)(bn + lrow) * K + lh;

    const uint32_t asB = smem_u32(&As[0][0]);
    const uint32_t bsB = smem_u32(&Bs[0][0]);
    const uint32_t ABUF = BM * LH * 2;
    const uint32_t BBUF = BN * LH * 2;
    uint32_t aAdr[2];
#pragma unroll
    for (int mt = 0; mt < 2; mt++) {
        int m0 = wm * 32 + mt * 16;
        aAdr[mt] = asB + (((m0 + (lane & 15)) * LH) + (lane >> 4) * 8) * 2;
    }
    uint32_t bAdr[4];
#pragma unroll
    for (int p = 0; p < 4; p++) {
        int n0 = wn * 64 + p * 16 + ((lane >> 4) << 3) + (lane & 7);
        bAdr[p] = bsB + (n0 * LH + (lane & 8)) * 2;
    }

    float acc[2][8][4];
#pragma unroll
    for (int mt = 0; mt < 2; mt++)
#pragma unroll
        for (int nt = 0; nt < 8; nt++)
#pragma unroll
            for (int r = 0; r < 4; r++) acc[mt][nt][r] = 0.f;

    float4 fa0, fa1, fb0, fb1;
    auto prefetch = [&](int s) {
        const int k0 = s * BK;
        fa0 = *(const float4*)(Ap + k0);
        fa1 = *(const float4*)(Ap + k0 + 4);
        fb0 = *(const float4*)(Bp + k0);
        fb1 = *(const float4*)(Bp + k0 + 4);
    };
    auto store = [&](int b) {
        uint4 va;
        va.x = pack2h(fa0.x, fa0.y); va.y = pack2h(fa0.z, fa0.w);
        va.z = pack2h(fa1.x, fa1.y); va.w = pack2h(fa1.z, fa1.w);
        *(uint4*)&As[b][lrow * LH + lh] = va;
        uint4 vb;
        vb.x = pack2h(fb0.x, fb0.y); vb.y = pack2h(fb0.z, fb0.w);
        vb.z = pack2h(fb1.x, fb1.y); vb.w = pack2h(fb1.z, fb1.w);
        *(uint4*)&Bs[b][lrow * LH + lh] = vb;
    };

    prefetch(0);
    store(0);
    __syncthreads();

    const int nst = K / BK;          // 32
    for (int s = 0; s < nst; s++) {
        const int b = s & 1;
        const uint32_t ao = b * ABUF, bo = b * BBUF;
        if (s + 1 < nst) prefetch(s + 1);

        uint32_t af[2][4];
#pragma unroll
        for (int mt = 0; mt < 2; mt++)
            LDSM_X4(af[mt][0], af[mt][1], af[mt][2], af[mt][3], aAdr[mt] + ao);
        uint32_t bf[8][2];
#pragma unroll
        for (int p = 0; p < 4; p++)
            LDSM_X4(bf[2 * p][0], bf[2 * p][1], bf[2 * p + 1][0], bf[2 * p + 1][1],
                    bAdr[p] + bo);

#pragma unroll
        for (int mt = 0; mt < 2; mt++)
#pragma unroll
            for (int nt = 0; nt < 8; nt++)
                mma_f16(acc[mt][nt], af[mt][0], af[mt][1], af[mt][2], af[mt][3],
                        bf[nt][0], bf[nt][1]);

        if (s + 1 < nst) {
            store(b ^ 1);
            __syncthreads();
        }
    }

    // Epilogue: fp16 half2 stores
#pragma unroll
    for (int mt = 0; mt < 2; mt++) {
        int r0 = bm + wm * 32 + mt * 16 + gid;
        int r1 = r0 + 8;
#pragma unroll
        for (int nt = 0; nt < 8; nt++) {
            int col = bn + wn * 64 + nt * 8 + tig * 2;
            if (r0 < M)
                *(__half2*)(C + (size_t)r0 * N + col) = __floats2half2_rn(acc[mt][nt][0], acc[mt][nt][1]);
            if (r1 < M)
                *(__half2*)(C + (size_t)r1 * N + col) = __floats2half2_rn(acc[mt][nt][2], acc[mt][nt][3]);
        }
    }
}

// ---------------------------------------------------------------------------
// Small-M fp32 GEMM (fp16 out): 16 cols/block x 16 lanes/col, shfl reduce.
// grid = (N/16, M). Full fp32 dot accuracy, chip-filling at tiny M.
// ---------------------------------------------------------------------------
__global__ void __launch_bounds__(256) small_gemm_tn(
    const float* __restrict__ A, const float* __restrict__ B,
    __half* __restrict__ C, int N, int K)
{
    __shared__ float Arow[FEAT_DIM];
    const int tid  = threadIdx.x;
    const int lane = tid & 31;
    const int wid  = tid >> 5;
    const int m    = blockIdx.y;

    if (tid < FEAT_DIM / 4)
        ((float4*)Arow)[tid] = ((const float4*)(A + (size_t)m * K))[tid];
    __syncthreads();

    const int col = blockIdx.x * 16 + wid * 2 + (lane >> 4);
    const int hl  = lane & 15;

    const float4* Br = (const float4*)(B + (size_t)col * K) + hl;
    const float4* Ar = (const float4*)Arow + hl;
    float s = 0.f;
#pragma unroll
    for (int i = 0; i < 8; i++) {
        float4 b = Br[i * 16];
        float4 a = Ar[i * 16];
        s += a.x * b.x + a.y * b.y + a.z * b.z + a.w * b.w;
    }
#pragma unroll
    for (int off = 8; off >= 1; off >>= 1)
        s += __shfl_xor_sync(0xffffffff, s, off);
    if (hl == 0)
        C[(size_t)m * N + col] = __float2half_rn(s);
}

// ---------------------------------------------------------------------------
// Per-level fused gate/elementwise kernel (fp16 intermediates in, fp32 out)
// ---------------------------------------------------------------------------
__device__ __forceinline__ float sigf(float x) { return 1.f / (1.f + expf(-x)); }
__device__ __forceinline__ float4 f4add(float4 a, float4 b) {
    return make_float4(a.x + b.x, a.y + b.y, a.z + b.z, a.w + b.w);
}
__device__ __forceinline__ float4 loadh4(const __half* p) {
    __half2 a = *(const __half2*)p;
    __half2 b = *(const __half2*)(p + 2);
    float2 fa = __half22float2(a), fb = __half22float2(b);
    return make_float4(fa.x, fa.y, fb.x, fb.y);
}

__global__ void __launch_bounds__(256) lstm_level_kernel(
    const float* __restrict__ iofux_b, const float* __restrict__ iofuh_b,
    const float* __restrict__ px_b, float* __restrict__ out,
    int start, int n, int hasPrev)
{
    int idx = blockIdx.x * 256 + threadIdx.x;
    int total = n * (H_DIM / 4);
    if (idx >= total) return;

    int j  = idx >> 7;
    int t4 = idx & 127;
    size_t g = (size_t)start + j;

    const __half* gx = g_iofux + g * GATE5 + t4 * 4;
    float4 vi = loadh4(gx);
    float4 vo = loadh4(gx + 512);
    float4 vf = loadh4(gx + 1024);
    float4 vu = loadh4(gx + 1536);
    float4 vr = loadh4(gx + 2048);

    float4 pc = make_float4(0.f, 0.f, 0.f, 0.f);
    if (hasPrev) {
        const __half* gh = g_hh + (size_t)(j >> 1) * GATE5 + t4 * 4;
        vi = f4add(vi, loadh4(gh));
        vo = f4add(vo, loadh4(gh + 512));
        vf = f4add(vf, loadh4(gh + 1024));
        vu = f4add(vu, loadh4(gh + 1536));
        vr = f4add(vr, loadh4(gh + 2048));
        size_t parent = (g - 1) >> 1;
        pc = ((const float4*)g_c)[parent * 128 + t4];
    }

    const float4* bx = (const float4*)iofux_b;
    const float4* bh = (const float4*)iofuh_b;
    vi = f4add(vi, f4add(bx[t4],       bh[t4]));
    vo = f4add(vo, f4add(bx[128 + t4], bh[128 + t4]));
    vf = f4add(vf, f4add(bx[256 + t4], bh[256 + t4]));
    vu = f4add(vu, f4add(bx[384 + t4], bh[384 + t4]));
    vr = f4add(vr, f4add(bx[512 + t4], bh[512 + t4]));

    float4 px4 = f4add(loadh4(g_px + g * H_DIM + t4 * 4),
                       ((const float4*)px_b)[t4]);

    float4 c4, h4;
#define GATE(C) {                                                     \
        float i_ = sigf(vi.C); float o_ = sigf(vo.C);                 \
        float f_ = sigf(vf.C); float u_ = tanhf(vu.C);                \
        float r_ = sigf(vr.C);                                        \
        float c_ = i_ * u_ + f_ * pc.C;                               \
        float h_ = o_ * tanhf(c_);                                    \
        c4.C = c_; h4.C = r_ * h_ + (1.f - r_) * px4.C; }
    GATE(x) GATE(y) GATE(z) GATE(w)
#undef GATE

    ((float4*)g_c)[g * 128 + t4] = c4;
    ((float4*)out)[g * 128 + t4] = h4;
}

// ---------------------------------------------------------------------------
// kernel_launch
// ---------------------------------------------------------------------------
extern "C" void kernel_launch(void* const* d_in, const int* in_sizes, int n_in,
                              void* d_out, int out_size)
{
    const float* features = (const float*)d_in[0];
    const float* px_w     = (const float*)d_in[1];
    const float* px_b     = (const float*)d_in[2];
    const float* iofux_w  = (const float*)d_in[3];
    const float* iofux_b  = (const float*)d_in[4];
    const float* iofuh_w  = (const float*)d_in[5];
    const float* iofuh_b  = (const float*)d_in[6];
    float* out = (float*)d_out;

    __half *iofux_p = nullptr, *px_p = nullptr, *hh_p = nullptr;
    cudaGetSymbolAddress((void**)&iofux_p, g_iofux);
    cudaGetSymbolAddress((void**)&px_p,    g_px);
    cudaGetSymbolAddress((void**)&hh_p,    g_hh);

    dim3 blk(256);

    // px = feats @ px_w.T   [N_NODES, 512]
    {
        dim3 grid(H_DIM / BN, (N_NODES + BM - 1) / BM);
        h16gemm_tn<<<grid, blk>>>(features, px_w, px_p, N_NODES, H_DIM, FEAT_DIM);
    }
    // iofux = feats @ iofux_w.T  [N_NODES, 2560]
    {
        dim3 grid(GATE5 / BN, (N_NODES + BM - 1) / BM);
        h16gemm_tn<<<grid, blk>>>(features, iofux_w, iofux_p, N_NODES, GATE5, FEAT_DIM);
    }

    for (int d = 0; d < DEPTH; d++) {
        int n = 1 << d;
        int start = n - 1;
        if (d > 0) {
            int Md = n >> 1;
            int startPrev = Md - 1;
            const float* Aprev = out + (size_t)startPrev * H_DIM;
            if (Md <= 256) {
                dim3 grid(GATE5 / 16, Md);
                small_gemm_tn<<<grid, 256>>>(Aprev, iofuh_w, hh_p, GATE5, FEAT_DIM);
            } else {
                dim3 grid(GATE5 / BN, (Md + BM - 1) / BM);
                h16gemm_tn<<<grid, blk>>>(Aprev, iofuh_w, hh_p, Md, GATE5, FEAT_DIM);
            }
        }
        int total = n * (H_DIM / 4);
        int nb = (total + 255) / 256;
        lstm_level_kernel<<<nb, blk>>>(iofux_b, iofuh_b, px_b, out,
                                       start, n, d > 0 ? 1 : 0);
    }
}

// round 12
// speedup vs baseline: 1.6807x; 1.4162x over previous
#include <cuda_runtime.h>
#include <cuda_fp16.h>
#include <math.h>
#include <stdint.h>

// Problem constants
#define FEAT_DIM 512
#define H_DIM    512
#define DEPTH    17
#define N_NODES  ((1 << DEPTH) - 1)   // 131071
#define GATE5    (5 * H_DIM)          // 2560
#define MAX_PREV (1 << (DEPTH - 2))   // 32768

// ---------------------------------------------------------------------------
// Scratch (static __device__ allocations)
// ---------------------------------------------------------------------------
__device__ __half g_iofux[(size_t)N_NODES * GATE5];   // 671 MB
__device__ __half g_px   [(size_t)N_NODES * H_DIM];   // 134 MB
__device__ float  g_c    [(size_t)N_NODES * H_DIM];   // 268 MB (fp32 recurrence)
__device__ __half g_hh   [(size_t)MAX_PREV * GATE5];  // 168 MB
__device__ __half g_feat16[(size_t)N_NODES * FEAT_DIM];  // 134 MB
__device__ __half g_h16   [(size_t)N_NODES * H_DIM];     // 134 MB
__device__ __half g_w_px   [H_DIM * FEAT_DIM];
__device__ __half g_w_iofux[GATE5 * FEAT_DIM];
__device__ __half g_w_iofuh[GATE5 * H_DIM];

__device__ __forceinline__ uint32_t smem_u32(const void* p) {
    uint32_t a;
    asm("{ .reg .u64 t; cvta.to.shared.u64 t, %1; cvt.u32.u64 %0, t; }" : "=r"(a) : "l"(p));
    return a;
}
__device__ __forceinline__ uint32_t pack2h(float lo, float hi) {
    __half2 h = __floats2half2_rn(lo, hi);
    return *(uint32_t*)&h;
}

// ---------------------------------------------------------------------------
// fp32 -> fp16 conversion (float4 granularity)
// ---------------------------------------------------------------------------
__global__ void __launch_bounds__(256) f2h_kernel(
    const float* __restrict__ in, __half* __restrict__ out, int n4)
{
    int i = blockIdx.x * 256 + threadIdx.x;
    if (i >= n4) return;
    float4 v = ((const float4*)in)[i];
    ((uint2*)out)[i] = make_uint2(pack2h(v.x, v.y), pack2h(v.z, v.w));
}

// ---------------------------------------------------------------------------
// fp16-in fp16-out mma GEMM, cp.async 3-stage, BK=32.
// C[M,N] = A[M,K] @ B[N,K]^T.  A,B fp16 row-major. K%32==0, N%128==0.
// Block 128x128, 8 warps, warp tile 32x64 (2x8 m16n8k16), fp32 accum.
// SMEM rows: 32 data halfs in 40-half (80B) stride -> conflict-free LDSM.
// ---------------------------------------------------------------------------
#define BM 128
#define BN 128
#define BK 32
#define LH 40                          // halfs per SMEM row
#define BUF_B (BM * LH * 2)            // 10240 bytes per matrix per stage
#define STAGE_B (2 * BUF_B)            // 20480
#define NSTAGE 3
#define SMEM_GEMM (NSTAGE * STAGE_B)   // 61440

__device__ __forceinline__ void mma_f16(float c[4],
                                        uint32_t a0, uint32_t a1, uint32_t a2, uint32_t a3,
                                        uint32_t b0, uint32_t b1)
{
    asm volatile(
        "mma.sync.aligned.m16n8k16.row.col.f32.f16.f16.f32 "
        "{%0,%1,%2,%3}, {%4,%5,%6,%7}, {%8,%9}, {%0,%1,%2,%3};\n"
        : "+f"(c[0]), "+f"(c[1]), "+f"(c[2]), "+f"(c[3])
        : "r"(a0), "r"(a1), "r"(a2), "r"(a3), "r"(b0), "r"(b1));
}
#define LDSM_X4(r0, r1, r2, r3, addr) \
    asm volatile("ldmatrix.sync.aligned.m8n8.x4.shared.b16 {%0,%1,%2,%3}, [%4];" \
                 : "=r"(r0), "=r"(r1), "=r"(r2), "=r"(r3) : "r"(addr))
#define CP_ASYNC16(dst, src) \
    asm volatile("cp.async.cg.shared.global [%0], [%1], 16;" :: "r"(dst), "l"(src) : "memory")
#define CP_COMMIT() asm volatile("cp.async.commit_group;" ::: "memory")
#define CP_WAIT2()  asm volatile("cp.async.wait_group 2;" ::: "memory")

__global__ void __launch_bounds__(256, 2) h16gemm_tn(
    const __half* __restrict__ A, const __half* __restrict__ B,
    __half* __restrict__ C, int M, int N, int K)
{
    extern __shared__ __align__(16) char sm[];
    const uint32_t sb = smem_u32(sm);

    const int tid  = threadIdx.x;
    const int lane = tid & 31;
    const int wid  = tid >> 5;
    const int wm   = wid & 3;        // warp row group (32 rows)
    const int wn   = wid >> 2;       // warp col group (64 cols)
    const int gid  = lane >> 2;
    const int tig  = lane & 3;
    const int bm   = blockIdx.y * BM;
    const int bn   = blockIdx.x * BN;

    // Loader: thread t -> row t>>1, two 16B chunks at byte (t&1)*32, +16
    const int lrow = tid >> 1;
    const int loff = (tid & 1) * 32;

    int ar = bm + lrow; if (ar >= M) ar = M - 1;
    const char* ApB = (const char*)(A + (size_t)ar * K) + loff;
    const char* BpB = (const char*)(B + (size_t)(bn + lrow) * K) + loff;
    const uint32_t dstA = sb + lrow * 80 + loff;          // + stage*STAGE_B
    const uint32_t dstB = sb + BUF_B + lrow * 80 + loff;

    // ldmatrix lane addresses (stage 0 base)
    uint32_t aAdr[2];
#pragma unroll
    for (int mt = 0; mt < 2; mt++) {
        int m0 = wm * 32 + mt * 16;
        aAdr[mt] = sb + (((m0 + (lane & 15)) * LH) + (lane >> 4) * 8) * 2;
    }
    uint32_t bAdr[4];
#pragma unroll
    for (int p = 0; p < 4; p++) {
        int n0 = wn * 64 + p * 16 + ((lane >> 4) << 3) + (lane & 7);
        bAdr[p] = sb + BUF_B + (n0 * LH + (lane & 8)) * 2;
    }

    float acc[2][8][4];
#pragma unroll
    for (int mt = 0; mt < 2; mt++)
#pragma unroll
        for (int nt = 0; nt < 8; nt++)
#pragma unroll
            for (int r = 0; r < 4; r++) acc[mt][nt][r] = 0.f;

    auto issue = [&](int s) {
        const uint32_t so = (uint32_t)(s % NSTAGE) * STAGE_B;
        const int kb = s * BK * 2;     // byte offset along K
        CP_ASYNC16(dstA + so,      ApB + kb);
        CP_ASYNC16(dstA + so + 16, ApB + kb + 16);
        CP_ASYNC16(dstB + so,      BpB + kb);
        CP_ASYNC16(dstB + so + 16, BpB + kb + 16);
        CP_COMMIT();
    };

    const int nst = K / BK;            // 16 for K=512
    issue(0);
    issue(1);

    for (int s = 0; s < nst; s++) {
        if (s + 2 < nst) issue(s + 2);
        else             CP_COMMIT();
        CP_WAIT2();
        __syncthreads();

        const uint32_t so = (uint32_t)(s % NSTAGE) * STAGE_B;
#pragma unroll
        for (int ks = 0; ks < 2; ks++) {
            const uint32_t ko = so + ks * 32;   // +16 halfs
            uint32_t af[2][4];
#pragma unroll
            for (int mt = 0; mt < 2; mt++)
                LDSM_X4(af[mt][0], af[mt][1], af[mt][2], af[mt][3], aAdr[mt] + ko);
            uint32_t bf[8][2];
#pragma unroll
            for (int p = 0; p < 4; p++)
                LDSM_X4(bf[2*p][0], bf[2*p][1], bf[2*p+1][0], bf[2*p+1][1], bAdr[p] + ko);
#pragma unroll
            for (int mt = 0; mt < 2; mt++)
#pragma unroll
                for (int nt = 0; nt < 8; nt++)
                    mma_f16(acc[mt][nt], af[mt][0], af[mt][1], af[mt][2], af[mt][3],
                            bf[nt][0], bf[nt][1]);
        }
        __syncthreads();
    }

    // Epilogue: fp16 half2 stores (validated mapping)
#pragma unroll
    for (int mt = 0; mt < 2; mt++) {
        int r0 = bm + wm * 32 + mt * 16 + gid;
        int r1 = r0 + 8;
#pragma unroll
        for (int nt = 0; nt < 8; nt++) {
            int col = bn + wn * 64 + nt * 8 + tig * 2;
            if (r0 < M)
                *(__half2*)(C + (size_t)r0 * N + col) = __floats2half2_rn(acc[mt][nt][0], acc[mt][nt][1]);
            if (r1 < M)
                *(__half2*)(C + (size_t)r1 * N + col) = __floats2half2_rn(acc[mt][nt][2], acc[mt][nt][3]);
        }
    }
}

// ---------------------------------------------------------------------------
// Small-M fp32 GEMM (fp16 out): 16 cols/block x 16 lanes/col, shfl reduce.
// grid = (N/16, M). Reads fp32 A (out buffer) and fp32 B (weights).
// ---------------------------------------------------------------------------
__global__ void __launch_bounds__(256) small_gemm_tn(
    const float* __restrict__ A, const float* __restrict__ B,
    __half* __restrict__ C, int N, int K)
{
    __shared__ float Arow[FEAT_DIM];
    const int tid  = threadIdx.x;
    const int lane = tid & 31;
    const int wid  = tid >> 5;
    const int m    = blockIdx.y;

    if (tid < FEAT_DIM / 4)
        ((float4*)Arow)[tid] = ((const float4*)(A + (size_t)m * K))[tid];
    __syncthreads();

    const int col = blockIdx.x * 16 + wid * 2 + (lane >> 4);
    const int hl  = lane & 15;

    const float4* Br = (const float4*)(B + (size_t)col * K) + hl;
    const float4* Ar = (const float4*)Arow + hl;
    float s = 0.f;
#pragma unroll
    for (int i = 0; i < 8; i++) {
        float4 b = Br[i * 16];
        float4 a = Ar[i * 16];
        s += a.x * b.x + a.y * b.y + a.z * b.z + a.w * b.w;
    }
#pragma unroll
    for (int off = 8; off >= 1; off >>= 1)
        s += __shfl_xor_sync(0xffffffff, s, off);
    if (hl == 0)
        C[(size_t)m * N + col] = __float2half_rn(s);
}

// ---------------------------------------------------------------------------
// Per-level fused gates: fp16 intermediates in, fp32 out + fp16 h copy.
// ---------------------------------------------------------------------------
__device__ __forceinline__ float sigf(float x) { return 1.f / (1.f + expf(-x)); }
__device__ __forceinline__ float4 f4add(float4 a, float4 b) {
    return make_float4(a.x + b.x, a.y + b.y, a.z + b.z, a.w + b.w);
}
__device__ __forceinline__ float4 loadh4(const __half* p) {
    __half2 a = *(const __half2*)p;
    __half2 b = *(const __half2*)(p + 2);
    float2 fa = __half22float2(a), fb = __half22float2(b);
    return make_float4(fa.x, fa.y, fb.x, fb.y);
}

__global__ void __launch_bounds__(256) lstm_level_kernel(
    const float* __restrict__ iofux_b, const float* __restrict__ iofuh_b,
    const float* __restrict__ px_b, float* __restrict__ out,
    int start, int n, int hasPrev)
{
    int idx = blockIdx.x * 256 + threadIdx.x;
    int total = n * (H_DIM / 4);
    if (idx >= total) return;

    int j  = idx >> 7;
    int t4 = idx & 127;
    size_t g = (size_t)start + j;

    const __half* gx = g_iofux + g * GATE5 + t4 * 4;
    float4 vi = loadh4(gx);
    float4 vo = loadh4(gx + 512);
    float4 vf = loadh4(gx + 1024);
    float4 vu = loadh4(gx + 1536);
    float4 vr = loadh4(gx + 2048);

    float4 pc = make_float4(0.f, 0.f, 0.f, 0.f);
    if (hasPrev) {
        const __half* gh = g_hh + (size_t)(j >> 1) * GATE5 + t4 * 4;
        vi = f4add(vi, loadh4(gh));
        vo = f4add(vo, loadh4(gh + 512));
        vf = f4add(vf, loadh4(gh + 1024));
        vu = f4add(vu, loadh4(gh + 1536));
        vr = f4add(vr, loadh4(gh + 2048));
        size_t parent = (g - 1) >> 1;
        pc = ((const float4*)g_c)[parent * 128 + t4];
    }

    const float4* bx = (const float4*)iofux_b;
    const float4* bh = (const float4*)iofuh_b;
    vi = f4add(vi, f4add(bx[t4],       bh[t4]));
    vo = f4add(vo, f4add(bx[128 + t4], bh[128 + t4]));
    vf = f4add(vf, f4add(bx[256 + t4], bh[256 + t4]));
    vu = f4add(vu, f4add(bx[384 + t4], bh[384 + t4]));
    vr = f4add(vr, f4add(bx[512 + t4], bh[512 + t4]));

    float4 px4 = f4add(loadh4(g_px + g * H_DIM + t4 * 4),
                       ((const float4*)px_b)[t4]);

    float4 c4, h4;
#define GATE(C) {                                                     \
        float i_ = sigf(vi.C); float o_ = sigf(vo.C);                 \
        float f_ = sigf(vf.C); float u_ = tanhf(vu.C);                \
        float r_ = sigf(vr.C);                                        \
        float c_ = i_ * u_ + f_ * pc.C;                               \
        float h_ = o_ * tanhf(c_);                                    \
        c4.C = c_; h4.C = r_ * h_ + (1.f - r_) * px4.C; }
    GATE(x) GATE(y) GATE(z) GATE(w)
#undef GATE

    ((float4*)g_c)[g * 128 + t4] = c4;
    ((float4*)out)[g * 128 + t4] = h4;
    // fp16 copy of h for next level's tensor GEMM
    *(uint2*)(g_h16 + g * H_DIM + t4 * 4) =
        make_uint2(pack2h(h4.x, h4.y), pack2h(h4.z, h4.w));
}

// ---------------------------------------------------------------------------
// kernel_launch
// ---------------------------------------------------------------------------
extern "C" void kernel_launch(void* const* d_in, const int* in_sizes, int n_in,
                              void* d_out, int out_size)
{
    const float* features = (const float*)d_in[0];
    const float* px_w     = (const float*)d_in[1];
    const float* px_b     = (const float*)d_in[2];
    const float* iofux_w  = (const float*)d_in[3];
    const float* iofux_b  = (const float*)d_in[4];
    const float* iofuh_w  = (const float*)d_in[5];
    const float* iofuh_b  = (const float*)d_in[6];
    float* out = (float*)d_out;

    __half *iofux_p, *px_p, *hh_p, *feat16, *h16, *w_px, *w_iofux, *w_iofuh;
    cudaGetSymbolAddress((void**)&iofux_p, g_iofux);
    cudaGetSymbolAddress((void**)&px_p,    g_px);
    cudaGetSymbolAddress((void**)&hh_p,    g_hh);
    cudaGetSymbolAddress((void**)&feat16,  g_feat16);
    cudaGetSymbolAddress((void**)&h16,     g_h16);
    cudaGetSymbolAddress((void**)&w_px,    g_w_px);
    cudaGetSymbolAddress((void**)&w_iofux, g_w_iofux);
    cudaGetSymbolAddress((void**)&w_iofuh, g_w_iofuh);

    cudaFuncSetAttribute(h16gemm_tn, cudaFuncAttributeMaxDynamicSharedMemorySize, SMEM_GEMM);

    dim3 blk(256);

    // fp32 -> fp16 conversions
    {
        int n4 = (N_NODES * FEAT_DIM) / 4;
        f2h_kernel<<<(n4 + 255) / 256, blk>>>(features, feat16, n4);
        n4 = (H_DIM * FEAT_DIM) / 4;
        f2h_kernel<<<(n4 + 255) / 256, blk>>>(px_w, w_px, n4);
        n4 = (GATE5 * FEAT_DIM) / 4;
        f2h_kernel<<<(n4 + 255) / 256, blk>>>(iofux_w, w_iofux, n4);
        n4 = (GATE5 * H_DIM) / 4;
        f2h_kernel<<<(n4 + 255) / 256, blk>>>(iofuh_w, w_iofuh, n4);
    }

    // px = feats @ px_w.T   [N_NODES, 512]
    {
        dim3 grid(H_DIM / BN, (N_NODES + BM - 1) / BM);
        h16gemm_tn<<<grid, blk, SMEM_GEMM>>>(feat16, w_px, px_p, N_NODES, H_DIM, FEAT_DIM);
    }
    // iofux = feats @ iofux_w.T  [N_NODES, 2560]
    {
        dim3 grid(GATE5 / BN, (N_NODES + BM - 1) / BM);
        h16gemm_tn<<<grid, blk, SMEM_GEMM>>>(feat16, w_iofux, iofux_p, N_NODES, GATE5, FEAT_DIM);
    }

    for (int d = 0; d < DEPTH; d++) {
        int n = 1 << d;
        int start = n - 1;
        if (d > 0) {
            int Md = n >> 1;
            int startPrev = Md - 1;
            if (Md <= 256) {
                const float* Aprev = out + (size_t)startPrev * H_DIM;
                dim3 grid(GATE5 / 16, Md);
                small_gemm_tn<<<grid, 256>>>(Aprev, iofuh_w, hh_p, GATE5, FEAT_DIM);
            } else {
                const __half* Aprev = h16 + (size_t)startPrev * H_DIM;
                dim3 grid(GATE5 / BN, (Md + BM - 1) / BM);
                h16gemm_tn<<<grid, blk, SMEM_GEMM>>>(Aprev, w_iofuh, hh_p, Md, GATE5, FEAT_DIM);
            }
        }
        int total = n * (H_DIM / 4);
        int nb = (total + 255) / 256;
        lstm_level_kernel<<<nb, blk>>>(iofux_b, iofuh_b, px_b, out,
                                       start, n, d > 0 ? 1 : 0);
    }
}

// round 13
// speedup vs baseline: 1.7245x; 1.0260x over previous
#include <cuda_runtime.h>
#include <cuda_fp16.h>
#include <math.h>
#include <stdint.h>

// Problem constants
#define FEAT_DIM 512
#define H_DIM    512
#define DEPTH    17
#define N_NODES  ((1 << DEPTH) - 1)   // 131071
#define GATE5    (5 * H_DIM)          // 2560
#define GXS      3072                 // combined row stride: 2560 iofu r + 512 px
#define MAX_PREV (1 << (DEPTH - 2))   // 32768

// ---------------------------------------------------------------------------
// Scratch (static __device__ allocations)
// ---------------------------------------------------------------------------
__device__ __half g_gx   [(size_t)N_NODES * GXS];      // 805 MB combined iofux|px
__device__ float  g_c    [(size_t)N_NODES * H_DIM];    // 268 MB (fp32 recurrence)
__device__ __half g_hh   [(size_t)MAX_PREV * GATE5];   // 168 MB
__device__ __half g_feat16[(size_t)N_NODES * FEAT_DIM];// 134 MB
__device__ __half g_h16   [(size_t)N_NODES * H_DIM];   // 134 MB
__device__ __half g_w_cat [GXS * FEAT_DIM];            // rows 0..2559 iofux, 2560..3071 px
__device__ __half g_w_iofuh[GATE5 * H_DIM];

__device__ __forceinline__ uint32_t smem_u32(const void* p) {
    uint32_t a;
    asm("{ .reg .u64 t; cvta.to.shared.u64 t, %1; cvt.u32.u64 %0, t; }" : "=r"(a) : "l"(p));
    return a;
}
__device__ __forceinline__ uint32_t pack2h(float lo, float hi) {
    __half2 h = __floats2half2_rn(lo, hi);
    return *(uint32_t*)&h;
}

// ---------------------------------------------------------------------------
// fp32 -> fp16 conversion, 4 float4 per thread (MLP=4)
// ---------------------------------------------------------------------------
__global__ void __launch_bounds__(256) f2h_kernel(
    const float* __restrict__ in, __half* __restrict__ out, int n4)
{
    int i0 = blockIdx.x * 1024 + threadIdx.x;
#pragma unroll
    for (int u = 0; u < 4; u++) {
        int i = i0 + u * 256;
        if (i < n4) {
            float4 v = ((const float4*)in)[i];
            ((uint2*)out)[i] = make_uint2(pack2h(v.x, v.y), pack2h(v.z, v.w));
        }
    }
}

// ---------------------------------------------------------------------------
// fp16-in fp16-out mma GEMM, cp.async 4-stage ring, one barrier per stage.
// C[M,N] = A[M,K] @ B[N,K]^T. Block 128x128, 8 warps, warp 32x64, fp32 accum.
// ---------------------------------------------------------------------------
#define BM 128
#define BN 128
#define BK 32
#define LH 40
#define BUF_B (BM * LH * 2)            // 10240
#define STAGE_B (2 * BUF_B)            // 20480
#define NSTAGE 4
#define SMEM_GEMM (NSTAGE * STAGE_B)   // 81920

__device__ __forceinline__ void mma_f16(float c[4],
                                        uint32_t a0, uint32_t a1, uint32_t a2, uint32_t a3,
                                        uint32_t b0, uint32_t b1)
{
    asm volatile(
        "mma.sync.aligned.m16n8k16.row.col.f32.f16.f16.f32 "
        "{%0,%1,%2,%3}, {%4,%5,%6,%7}, {%8,%9}, {%0,%1,%2,%3};\n"
        : "+f"(c[0]), "+f"(c[1]), "+f"(c[2]), "+f"(c[3])
        : "r"(a0), "r"(a1), "r"(a2), "r"(a3), "r"(b0), "r"(b1));
}
#define LDSM_X4(r0, r1, r2, r3, addr) \
    asm volatile("ldmatrix.sync.aligned.m8n8.x4.shared.b16 {%0,%1,%2,%3}, [%4];" \
                 : "=r"(r0), "=r"(r1), "=r"(r2), "=r"(r3) : "r"(addr))
#define CP_ASYNC16(dst, src) \
    asm volatile("cp.async.cg.shared.global [%0], [%1], 16;" :: "r"(dst), "l"(src) : "memory")
#define CP_COMMIT() asm volatile("cp.async.commit_group;" ::: "memory")
#define CP_WAIT2()  asm volatile("cp.async.wait_group 2;" ::: "memory")

__global__ void __launch_bounds__(256, 2) h16gemm_tn(
    const __half* __restrict__ A, const __half* __restrict__ B,
    __half* __restrict__ C, int M, int N, int K)
{
    extern __shared__ __align__(16) char sm[];
    const uint32_t sb = smem_u32(sm);

    const int tid  = threadIdx.x;
    const int lane = tid & 31;
    const int wid  = tid >> 5;
    const int wm   = wid & 3;
    const int wn   = wid >> 2;
    const int gid  = lane >> 2;
    const int tig  = lane & 3;
    const int bm   = blockIdx.y * BM;
    const int bn   = blockIdx.x * BN;

    const int lrow = tid >> 1;
    const int loff = (tid & 1) * 32;

    int ar = bm + lrow; if (ar >= M) ar = M - 1;
    const char* ApB = (const char*)(A + (size_t)ar * K) + loff;
    const char* BpB = (const char*)(B + (size_t)(bn + lrow) * K) + loff;
    const uint32_t dstA = sb + lrow * 80 + loff;
    const uint32_t dstB = sb + BUF_B + lrow * 80 + loff;

    uint32_t aAdr[2];
#pragma unroll
    for (int mt = 0; mt < 2; mt++) {
        int m0 = wm * 32 + mt * 16;
        aAdr[mt] = sb + (((m0 + (lane & 15)) * LH) + (lane >> 4) * 8) * 2;
    }
    uint32_t bAdr[4];
#pragma unroll
    for (int p = 0; p < 4; p++) {
        int n0 = wn * 64 + p * 16 + ((lane >> 4) << 3) + (lane & 7);
        bAdr[p] = sb + BUF_B + (n0 * LH + (lane & 8)) * 2;
    }

    float acc[2][8][4];
#pragma unroll
    for (int mt = 0; mt < 2; mt++)
#pragma unroll
        for (int nt = 0; nt < 8; nt++)
#pragma unroll
            for (int r = 0; r < 4; r++) acc[mt][nt][r] = 0.f;

    auto issue = [&](int s) {
        const uint32_t so = (uint32_t)(s % NSTAGE) * STAGE_B;
        const int kb = s * BK * 2;
        CP_ASYNC16(dstA + so,      ApB + kb);
        CP_ASYNC16(dstA + so + 16, ApB + kb + 16);
        CP_ASYNC16(dstB + so,      BpB + kb);
        CP_ASYNC16(dstB + so + 16, BpB + kb + 16);
        CP_COMMIT();
    };

    const int nst = K / BK;
    issue(0);
    issue(1);

    for (int s = 0; s < nst; s++) {
        // Writes buffer (s+2)%4, last read at stage s-2: separated from those
        // readers by the mid-iteration barrier below (safe with NSTAGE>=4).
        if (s + 2 < nst) issue(s + 2);
        else             CP_COMMIT();
        CP_WAIT2();
        __syncthreads();

        const uint32_t so = (uint32_t)(s % NSTAGE) * STAGE_B;
#pragma unroll
        for (int ks = 0; ks < 2; ks++) {
            const uint32_t ko = so + ks * 32;
            uint32_t af[2][4];
#pragma unroll
            for (int mt = 0; mt < 2; mt++)
                LDSM_X4(af[mt][0], af[mt][1], af[mt][2], af[mt][3], aAdr[mt] + ko);
            uint32_t bf[8][2];
#pragma unroll
            for (int p = 0; p < 4; p++)
                LDSM_X4(bf[2*p][0], bf[2*p][1], bf[2*p+1][0], bf[2*p+1][1], bAdr[p] + ko);
#pragma unroll
            for (int mt = 0; mt < 2; mt++)
#pragma unroll
                for (int nt = 0; nt < 8; nt++)
                    mma_f16(acc[mt][nt], af[mt][0], af[mt][1], af[mt][2], af[mt][3],
                            bf[nt][0], bf[nt][1]);
        }
    }

#pragma unroll
    for (int mt = 0; mt < 2; mt++) {
        int r0 = bm + wm * 32 + mt * 16 + gid;
        int r1 = r0 + 8;
#pragma unroll
        for (int nt = 0; nt < 8; nt++) {
            int col = bn + wn * 64 + nt * 8 + tig * 2;
            if (r0 < M)
                *(__half2*)(C + (size_t)r0 * N + col) = __floats2half2_rn(acc[mt][nt][0], acc[mt][nt][1]);
            if (r1 < M)
                *(__half2*)(C + (size_t)r1 * N + col) = __floats2half2_rn(acc[mt][nt][2], acc[mt][nt][3]);
        }
    }
}

// ---------------------------------------------------------------------------
// Small-M fp32 GEMM (fp16 out): 16 cols/block x 16 lanes/col, shfl reduce.
// ---------------------------------------------------------------------------
__global__ void __launch_bounds__(256) small_gemm_tn(
    const float* __restrict__ A, const float* __restrict__ B,
    __half* __restrict__ C, int N, int K)
{
    __shared__ float Arow[FEAT_DIM];
    const int tid  = threadIdx.x;
    const int lane = tid & 31;
    const int wid  = tid >> 5;
    const int m    = blockIdx.y;

    if (tid < FEAT_DIM / 4)
        ((float4*)Arow)[tid] = ((const float4*)(A + (size_t)m * K))[tid];
    __syncthreads();

    const int col = blockIdx.x * 16 + wid * 2 + (lane >> 4);
    const int hl  = lane & 15;

    const float4* Br = (const float4*)(B + (size_t)col * K) + hl;
    const float4* Ar = (const float4*)Arow + hl;
    float s = 0.f;
#pragma unroll
    for (int i = 0; i < 8; i++) {
        float4 b = Br[i * 16];
        float4 a = Ar[i * 16];
        s += a.x * b.x + a.y * b.y + a.z * b.z + a.w * b.w;
    }
#pragma unroll
    for (int off = 8; off >= 1; off >>= 1)
        s += __shfl_xor_sync(0xffffffff, s, off);
    if (hl == 0)
        C[(size_t)m * N + col] = __float2half_rn(s);
}

// ---------------------------------------------------------------------------
// Per-level fused gates: combined gx (iofu r | px) fp16 in, fp32 out + h16.
// ---------------------------------------------------------------------------
__device__ __forceinline__ float sigf(float x) { return 1.f / (1.f + expf(-x)); }
__device__ __forceinline__ float4 f4add(float4 a, float4 b) {
    return make_float4(a.x + b.x, a.y + b.y, a.z + b.z, a.w + b.w);
}
__device__ __forceinline__ float4 loadh4(const __half* p) {
    __half2 a = *(const __half2*)p;
    __half2 b = *(const __half2*)(p + 2);
    float2 fa = __half22float2(a), fb = __half22float2(b);
    return make_float4(fa.x, fa.y, fb.x, fb.y);
}

__global__ void __launch_bounds__(256) lstm_level_kernel(
    const float* __restrict__ iofux_b, const float* __restrict__ iofuh_b,
    const float* __restrict__ px_b, float* __restrict__ out,
    int start, int n, int hasPrev)
{
    int idx = blockIdx.x * 256 + threadIdx.x;
    int total = n * (H_DIM / 4);
    if (idx >= total) return;

    int j  = idx >> 7;
    int t4 = idx & 127;
    size_t g = (size_t)start + j;

    const __half* gx = g_gx + g * GXS + t4 * 4;
    float4 vi = loadh4(gx);
    float4 vo = loadh4(gx + 512);
    float4 vf = loadh4(gx + 1024);
    float4 vu = loadh4(gx + 1536);
    float4 vr = loadh4(gx + 2048);

    float4 pc = make_float4(0.f, 0.f, 0.f, 0.f);
    if (hasPrev) {
        const __half* gh = g_hh + (size_t)(j >> 1) * GATE5 + t4 * 4;
        vi = f4add(vi, loadh4(gh));
        vo = f4add(vo, loadh4(gh + 512));
        vf = f4add(vf, loadh4(gh + 1024));
        vu = f4add(vu, loadh4(gh + 1536));
        vr = f4add(vr, loadh4(gh + 2048));
        size_t parent = (g - 1) >> 1;
        pc = ((const float4*)g_c)[parent * 128 + t4];
    }

    const float4* bx = (const float4*)iofux_b;
    const float4* bh = (const float4*)iofuh_b;
    vi = f4add(vi, f4add(bx[t4],       bh[t4]));
    vo = f4add(vo, f4add(bx[128 + t4], bh[128 + t4]));
    vf = f4add(vf, f4add(bx[256 + t4], bh[256 + t4]));
    vu = f4add(vu, f4add(bx[384 + t4], bh[384 + t4]));
    vr = f4add(vr, f4add(bx[512 + t4], bh[512 + t4]));

    float4 px4 = f4add(loadh4(gx + 2560), ((const float4*)px_b)[t4]);

    float4 c4, h4;
#define GATE(C) {                                                     \
        float i_ = sigf(vi.C); float o_ = sigf(vo.C);                 \
        float f_ = sigf(vf.C); float u_ = tanhf(vu.C);                \
        float r_ = sigf(vr.C);                                        \
        float c_ = i_ * u_ + f_ * pc.C;                               \
        float h_ = o_ * tanhf(c_);                                    \
        c4.C = c_; h4.C = r_ * h_ + (1.f - r_) * px4.C; }
    GATE(x) GATE(y) GATE(z) GATE(w)
#undef GATE

    ((float4*)g_c)[g * 128 + t4] = c4;
    ((float4*)out)[g * 128 + t4] = h4;
    *(uint2*)(g_h16 + g * H_DIM + t4 * 4) =
        make_uint2(pack2h(h4.x, h4.y), pack2h(h4.z, h4.w));
}

// ---------------------------------------------------------------------------
// kernel_launch: conversions -> fork (per-level GEMM chunks on s2) -> join
// recurrence waits on its level's chunk event.
// ---------------------------------------------------------------------------
extern "C" void kernel_launch(void* const* d_in, const int* in_sizes, int n_in,
                              void* d_out, int out_size)
{
    const float* features = (const float*)d_in[0];
    const float* px_w     = (const float*)d_in[1];
    const float* px_b     = (const float*)d_in[2];
    const float* iofux_w  = (const float*)d_in[3];
    const float* iofux_b  = (const float*)d_in[4];
    const float* iofuh_w  = (const float*)d_in[5];
    const float* iofuh_b  = (const float*)d_in[6];
    float* out = (float*)d_out;

    __half *gx_p, *hh_p, *feat16, *h16, *w_cat, *w_iofuh;
    cudaGetSymbolAddress((void**)&gx_p,    g_gx);
    cudaGetSymbolAddress((void**)&hh_p,    g_hh);
    cudaGetSymbolAddress((void**)&feat16,  g_feat16);
    cudaGetSymbolAddress((void**)&h16,     g_h16);
    cudaGetSymbolAddress((void**)&w_cat,   g_w_cat);
    cudaGetSymbolAddress((void**)&w_iofuh, g_w_iofuh);

    // Streams/events created once on the first (uncaptured) correctness call.
    static cudaStream_t s2 = nullptr;
    static cudaEvent_t evConv = nullptr;
    static cudaEvent_t evChunk[7];
    if (!s2) {
        cudaStreamCreateWithFlags(&s2, cudaStreamNonBlocking);
        cudaEventCreateWithFlags(&evConv, cudaEventDisableTiming);
        for (int i = 0; i < 7; i++)
            cudaEventCreateWithFlags(&evChunk[i], cudaEventDisableTiming);
        cudaFuncSetAttribute(h16gemm_tn, cudaFuncAttributeMaxDynamicSharedMemorySize, SMEM_GEMM);
    }

    dim3 blk(256);

    // fp32 -> fp16 conversions (main stream)
    {
        int n4 = (N_NODES * FEAT_DIM) / 4;
        f2h_kernel<<<(n4 + 1023) / 1024, blk>>>(features, feat16, n4);
        n4 = (GATE5 * FEAT_DIM) / 4;
        f2h_kernel<<<(n4 + 1023) / 1024, blk>>>(iofux_w, w_cat, n4);
        n4 = (H_DIM * FEAT_DIM) / 4;
        f2h_kernel<<<(n4 + 1023) / 1024, blk>>>(px_w, w_cat + (size_t)GATE5 * FEAT_DIM, n4);
        n4 = (GATE5 * H_DIM) / 4;
        f2h_kernel<<<(n4 + 1023) / 1024, blk>>>(iofuh_w, w_iofuh, n4);
    }

    // Fork: per-level-chunk combined GEMM gx = feats @ [iofux_w|px_w].T on s2
    cudaEventRecord(evConv, 0);
    cudaStreamWaitEvent(s2, evConv, 0);
    {
        // chunk 0: levels d=0..10 (rows 0..2046)
        int r0 = 0, mrows = 2047;
        dim3 grid(GXS / BN, (mrows + BM - 1) / BM);
        h16gemm_tn<<<grid, blk, SMEM_GEMM, s2>>>(
            feat16 + (size_t)r0 * FEAT_DIM, w_cat, gx_p + (size_t)r0 * GXS,
            mrows, GXS, FEAT_DIM);
        cudaEventRecord(evChunk[0], s2);
        for (int d = 11; d < DEPTH; d++) {
            r0 = (1 << d) - 1; mrows = 1 << d;
            dim3 g2(GXS / BN, (mrows + BM - 1) / BM);
            h16gemm_tn<<<g2, blk, SMEM_GEMM, s2>>>(
                feat16 + (size_t)r0 * FEAT_DIM, w_cat, gx_p + (size_t)r0 * GXS,
                mrows, GXS, FEAT_DIM);
            cudaEventRecord(evChunk[d - 10], s2);
        }
    }

    // Recurrence on main stream
    for (int d = 0; d < DEPTH; d++) {
        int n = 1 << d;
        int start = n - 1;
        if (d > 0) {
            int Md = n >> 1;
            int startPrev = Md - 1;
            if (Md <= 256) {
                const float* Aprev = out + (size_t)startPrev * H_DIM;
                dim3 grid(GATE5 / 16, Md);
                small_gemm_tn<<<grid, 256>>>(Aprev, iofuh_w, hh_p, GATE5, FEAT_DIM);
            } else {
                const __half* Aprev = h16 + (size_t)startPrev * H_DIM;
                dim3 grid(GATE5 / BN, (Md + BM - 1) / BM);
                h16gemm_tn<<<grid, blk, SMEM_GEMM>>>(Aprev, w_iofuh, hh_p, Md, GATE5, FEAT_DIM);
            }
        }
        // wait for this level's gx chunk
        int ci = (d <= 10) ? 0 : d - 10;
        cudaStreamWaitEvent(0, evChunk[ci], 0);

        int total = n * (H_DIM / 4);
        int nb = (total + 255) / 256;
        lstm_level_kernel<<<nb, blk>>>(iofux_b, iofuh_b, px_b, out,
                                       start, n, d > 0 ? 1 : 0);
    }
}